// round 15
// baseline (speedup 1.0000x reference)
#include <cuda_runtime.h>

// x <- gelu(x + depthwise_conv3d_3x3x3(x)) x8.  [4,32,64,64,64] fp32.
// Fused 8-step cluster kernel. 128 threads = 4 INDEPENDENT warp-pipelines:
// warp-private slabs (6 H-rows each, +2-row overlap), __syncwarp only,
// depth-2 cp.async (wait_group 1), centers carried in registers.

#define CC    32
#define VOL   (64*64*64)
#define RSB   288                // bytes per slab row (72 words)
#define WBUF  2048               // bytes per plane buffer per warp
#define W3    (3*WBUF)           // 3 rotating buffers per warp

typedef unsigned long long u64;
typedef unsigned int u32;

__device__ float  g_sA[4 * CC * VOL];
__device__ float  g_sB[4 * CC * VOL];
__device__ __align__(16) float4 g_zero4 = {0.f, 0.f, 0.f, 0.f};

// ---------- packed f32x2 helpers ----------
__device__ __forceinline__ u64 pack2(float lo, float hi) {
    u64 r; asm("mov.b64 %0, {%1, %2};" : "=l"(r) : "f"(lo), "f"(hi)); return r;
}
__device__ __forceinline__ void unpack2(u64 v, float& lo, float& hi) {
    asm("mov.b64 {%0, %1}, %2;" : "=f"(lo), "=f"(hi) : "l"(v));
}
__device__ __forceinline__ void fma2(u64& acc, u64 a, u64 b) {
    asm("fma.rn.f32x2 %0, %1, %2, %0;" : "+l"(acc) : "l"(a), "l"(b));
}
__device__ __forceinline__ void mul2(u64& d, u64 a, u64 b) {
    asm("mul.rn.f32x2 %0, %1, %2;" : "=l"(d) : "l"(a), "l"(b));
}
__device__ __forceinline__ u64 add2(u64 a, u64 b) {
    u64 r; asm("add.rn.f32x2 %0, %1, %2;" : "=l"(r) : "l"(a), "l"(b)); return r;
}

// ---------- volatile SMEM loads (addresses repeat every 3 windows) ----------
#define LDSP(x, y, base, IMM)                                            \
    asm volatile("ld.shared.v2.u64 {%0, %1}, [%2+%3];"                   \
                 : "=l"(x), "=l"(y) : "r"(base), "n"(IMM))
#define LDS1(x, base, IMM)                                               \
    asm volatile("ld.shared.u64 %0, [%1+%2];"                            \
                 : "=l"(x) : "r"(base), "n"(IMM))

// ---------- cp.async ----------
#define CPA16(dst, src)                                                  \
    asm volatile("cp.async.cg.shared.global [%0], [%1], 16;"             \
                 :: "r"(dst), "l"(src))
#define CPCOMMIT() asm volatile("cp.async.commit_group;")
#define CPWAIT0()  asm volatile("cp.async.wait_group 0;")
#define CPWAIT1()  asm volatile("cp.async.wait_group 1;")

// Exact-erf GELU via A&S 7.1.27 (abs err ~3e-7; tol 1e-3). One MUFU.
__device__ __forceinline__ float gelu16(float x) {
    float a = fabsf(x) * 0.70710678118654752440f;
    float p = fmaf(0.0000430638f, a, 0.0002765672f);
    p = fmaf(p, a, 0.0001520143f);
    p = fmaf(p, a, 0.0092705272f);
    p = fmaf(p, a, 0.0422820123f);
    p = fmaf(p, a, 0.0705230784f);
    p = fmaf(p, a, 1.0f);
    float r; asm("rcp.approx.f32 %0, %1;" : "=f"(r) : "f"(p));
    r = r * r; r = r * r; r = r * r; r = r * r;      // p^-16
    float er = 1.0f - r;
    er = copysignf(er, x);
    return 0.5f * fmaf(x, er, x);
}

// One input row's 5 stencil windows: 2x LDS.64 edges + 1x LDS.128 center.
#define LOADQ(OFF)                                                       \
    u64 E1, Q1, Q3, F0;                                                  \
    LDS1(E1, rC, (OFF) + 8);                                             \
    LDSP(Q1, Q3, rC, (OFF) + 16);                                        \
    LDS1(F0, rC, (OFF) + 32);                                            \
    float fm, fp, f0, f1, f2, f3, dm0, dm1;                              \
    unpack2(E1, dm0, fm);                                                \
    unpack2(F0, fp, dm1);                                                \
    unpack2(Q1, f0, f1);                                                 \
    unpack2(Q3, f2, f3);                                                 \
    u64 Q0 = pack2(fm, f0), Q2 = pack2(f1, f2), Q4 = pack2(f3, fp);      \
    (void)dm0; (void)dm1;

#define FMA6(S0, S1, WB)                                                 \
    fma2(S0, W2[(WB)+0], Q0); fma2(S1, W2[(WB)+0], Q2);                  \
    fma2(S0, W2[(WB)+1], Q1); fma2(S1, W2[(WB)+1], Q3);                  \
    fma2(S0, W2[(WB)+2], Q2); fma2(S1, W2[(WB)+2], Q4);
#define MUL6(S0, S1, WB)                                                 \
    mul2(S0, W2[(WB)+0], Q0); mul2(S1, W2[(WB)+0], Q2);                  \
    fma2(S0, W2[(WB)+1], Q1); fma2(S1, W2[(WB)+1], Q3);                  \
    fma2(S0, W2[(WB)+2], Q2); fma2(S1, W2[(WB)+2], Q4);

// Locals use reserved _names (macro-capture bug class, round 12).
#define STORE4(A0, A1, C0, C1, PTR)                                      \
    {                                                                    \
        u64 _t0 = add2(A0, C0), _t1 = add2(A1, C1);                      \
        float _o0, _o1, _o2, _o3;                                        \
        unpack2(_t0, _o0, _o1); unpack2(_t1, _o2, _o3);                  \
        float4 _ov = make_float4(gelu16(_o0), gelu16(_o1),               \
                                 gelu16(_o2), gelu16(_o3));              \
        *(float4*)(PTR) = _ov;                                           \
    }

// One plane at buffer offset SB: 4 LOADQ rows -> 2 output rows.
// X completes (kz2), Y mid (kz1), Z fresh (kz0). Captures this plane's
// residual centers (Q1,Q3 at rows 1,2) into CV quad.
#define PLANE(SB, X0,X1,X2,X3, Y0,Y1,Y2,Y3, Z0,Z1,Z2,Z3, CV0,CV1,CV2,CV3) \
    { LOADQ((SB))           MUL6(Z0,Z1,0)  FMA6(Y0,Y1,9)   FMA6(X0,X1,18) } \
    { LOADQ((SB) + RSB)     CV0 = Q1; CV1 = Q3;                           \
                            FMA6(X0,X1,21) FMA6(Y0,Y1,12)  FMA6(Z0,Z1,3)  \
                            MUL6(Z2,Z3,0)  FMA6(Y2,Y3,9)   FMA6(X2,X3,18) } \
    { LOADQ((SB) + 2*RSB)   CV2 = Q1; CV3 = Q3;                           \
                            FMA6(X0,X1,24) FMA6(Y0,Y1,15)  FMA6(Z0,Z1,6)  \
                            FMA6(X2,X3,21) FMA6(Y2,Y3,12)  FMA6(Z2,Z3,3) } \
    { LOADQ((SB) + 3*RSB)   FMA6(X2,X3,24) FMA6(Y2,Y3,15)  FMA6(Z2,Z3,6) }

// Window p: wait (plane p resident; WAITN=1 keeps plane p+1 in flight),
// warp-sync, prefetch plane p+2 into SBN, compute plane p from SB,
// store out(p-1) with carried centers, carry plane-p centers.
#define WINDOW(SB, SBN, X0,X1,X2,X3, Y0,Y1,Y2,Y3, Z0,Z1,Z2,Z3, DOST, DOPF, WAITN) \
    do {                                                                 \
        if ((WAITN) == 0) CPWAIT0(); else CPWAIT1();                     \
        __syncwarp();                                                    \
        if (DOPF) {                                                      \
            CPA16(d0 + (SBN), pa0); CPA16(d1 + (SBN), pa1);              \
            CPA16(d2 + (SBN), pa2);                                      \
            CPCOMMIT();                                                  \
            pa0 += st0; pa1 += st1; pa2 += st2;                          \
        }                                                                \
        u64 cv0, cv1, cv2, cv3;                                          \
        PLANE((SB), X0,X1,X2,X3, Y0,Y1,Y2,Y3, Z0,Z1,Z2,Z3,               \
              cv0,cv1,cv2,cv3)                                           \
        if (DOST) {                                                      \
            STORE4(X0, X1, cen0, cen1, optr);                            \
            STORE4(X2, X3, cen2, cen3, optr + 64);                       \
            optr += 4096;                                                \
        }                                                                \
        cen0 = cv0; cen1 = cv1; cen2 = cv2; cen3 = cv3;                  \
    } while (0)

// Cluster of 4 = the 4 H-chunks of one (b,c); halos only cross H-chunks.
__global__ void __launch_bounds__(128, 4) __cluster_dims__(4, 1, 1)
fused_kernel(const float* __restrict__ x, float* __restrict__ outF,
             const float* __restrict__ wts,
             float* __restrict__ sA, float* __restrict__ sB)
{
    const int tid  = threadIdx.x;            // 0..127
    const int w    = tid >> 5;               // warp 0..3
    const int lane = tid & 31;
    const int tyl  = lane >> 4;              // 0/1: output row pair within warp
    const int tx   = lane & 15;              // w quad
    const int h0   = blockIdx.x * 16;
    const int c    = blockIdx.y;
    const int b    = blockIdx.z;
    const size_t volOff = (size_t)(b * CC + c) * VOL;

    u64 W2[27];
#pragma unroll
    for (int i = 0; i < 27; ++i) {
        float ww = __ldg(&wts[c * 27 + i]);
        W2[i] = pack2(ww, ww);
    }

    // Warp-private slabs: 4 warps x 3 buffers x 6 rows x 72 words (row:
    // word3 = left halo 0, 4..67 data, 68 = right halo 0). 24.5 KB total.
    __shared__ __align__(16) float sl[4 * (W3 / 4)];

    // Each warp zeroes its own halo words (3 bufs x 6 rows x 2 words = 36).
    for (int i = lane; i < 36; i += 32) {
        int buf = i / 12, k = i % 12;
        sl[w * (W3/4) + buf * (WBUF/4) + (k % 6) * 72 + (k < 6 ? 3 : 68)] = 0.f;
    }
    __syncwarp();

    const u32 sbase = (u32)__cvta_generic_to_shared(sl) + w * W3;
    // Compute read base: output pair rows = warp slab rows 2tyl..2tyl+3.
    const u32 rC = sbase + (2 * tyl) * RSB + 16 * tx;

    // Loader: lane owns 16B chunks of warp slab rows rb, rb+2, rb+4.
    const int rb  = lane >> 4;
    const int gh0 = h0 + 4 * w - 1 + rb;
    const int gh1 = gh0 + 2;
    const int gh2 = gh0 + 4;
    const bool v0 = (gh0 >= 0) && (gh0 < 64);
    const bool v1 = (gh1 >= 0) && (gh1 < 64);
    const bool v2 = (gh2 < 64);              // gh2 >= 3 always
    const int of0 = gh0 * 16 + tx, of1 = gh1 * 16 + tx, of2 = gh2 * 16 + tx;
    const int st0 = v0 ? 1024 : 0, st1 = v1 ? 1024 : 0, st2 = v2 ? 1024 : 0;

    const u32 d0 = sbase + rb * RSB + 16 + 16 * tx;          // row rb, word 4+4tx
    const u32 d1 = d0 + 2 * RSB;
    const u32 d2 = d0 + 4 * RSB;

    const int outOfs = (h0 + 4 * w + 2 * tyl) * 64 + 4 * tx;

    const float* sin = x;

#pragma unroll 1
    for (int s = 0; s < 8; ++s) {
        float* sout = (s == 7) ? outF : ((s & 1) ? sB : sA);
        const float* vin = sin + volOff;

        const float4* pa0 = v0 ? (const float4*)vin + of0 : &g_zero4;
        const float4* pa1 = v1 ? (const float4*)vin + of1 : &g_zero4;
        const float4* pa2 = v2 ? (const float4*)vin + of2 : &g_zero4;
        float* optr = (sout + volOff) + outOfs;

        // Prologue: planes 0,1 -> buffers 0,1 (two groups in flight).
        CPA16(d0, pa0); CPA16(d1, pa1); CPA16(d2, pa2);
        CPCOMMIT();
        CPA16(d0 + WBUF, pa0 + st0); CPA16(d1 + WBUF, pa1 + st1);
        CPA16(d2 + WBUF, pa2 + st2);
        CPCOMMIT();
        pa0 += 2 * st0; pa1 += 2 * st1; pa2 += 2 * st2;

        // Rotating accumulator quads + carried center quad.
        u64 s00=0,s01=0,s02=0,s03=0, s10=0,s11=0,s12=0,s13=0,
            s20=0,s21=0,s22=0,s23=0;
        u64 cen0=0, cen1=0, cen2=0, cen3=0;

        // Window p: X=s[(p+2)%3], Y=s[p%3], Z=s[(p+1)%3];
        // SB=(p%3)*WBUF, SBN=((p+2)%3)*WBUF.
        WINDOW(0, 2*WBUF, s20,s21,s22,s23, s00,s01,s02,s03,
               s10,s11,s12,s13, false, true, 1);                     // p=0
#pragma unroll 1
        for (int i = 0; i < 20; ++i) {                               // p=1..60
            WINDOW(WBUF, 0, s00,s01,s02,s03, s10,s11,s12,s13,
                   s20,s21,s22,s23, true, true, 1);                  // p%3==1
            WINDOW(2*WBUF, WBUF, s10,s11,s12,s13, s20,s21,s22,s23,
                   s00,s01,s02,s03, true, true, 1);                  // p%3==2
            WINDOW(0, 2*WBUF, s20,s21,s22,s23, s00,s01,s02,s03,
                   s10,s11,s12,s13, true, true, 1);                  // p%3==0
        }
        WINDOW(WBUF, 0, s00,s01,s02,s03, s10,s11,s12,s13,
               s20,s21,s22,s23, true, true, 1);                      // p=61
        WINDOW(2*WBUF, WBUF, s10,s11,s12,s13, s20,s21,s22,s23,
               s00,s01,s02,s03, true, false, 1);                     // p=62
        WINDOW(0, 2*WBUF, s20,s21,s22,s23, s00,s01,s02,s03,
               s10,s11,s12,s13, true, false, 0);                     // p=63

        // out(63): kz2 (plane 64) = 0; partial = Y of w63 = s0 quad;
        // centers = plane 63's, carried in cen after w63.
        STORE4(s00, s01, cen0, cen1, optr);
        STORE4(s02, s03, cen2, cen3, optr + 64);

        if (s < 7) {
            __threadfence();
            asm volatile("barrier.cluster.arrive.aligned;" ::: "memory");
            asm volatile("barrier.cluster.wait.aligned;"   ::: "memory");
        }
        sin = sout;
    }
}

extern "C" void kernel_launch(void* const* d_in, const int* in_sizes, int n_in,
                              void* d_out, int out_size)
{
    const float* x = (const float*)d_in[0];
    const float* w = (const float*)d_in[1];
    float* out = (float*)d_out;

    float *sA = nullptr, *sB = nullptr;
    cudaGetSymbolAddress((void**)&sA, g_sA);
    cudaGetSymbolAddress((void**)&sB, g_sB);

    dim3 grid(4, CC, 4);    // x-dim (H-chunks) grouped into clusters of 4
    dim3 blk(128);
    fused_kernel<<<grid, blk>>>(x, out, w, sA, sB);
}

// round 16
// speedup vs baseline: 1.0159x; 1.0159x over previous
#include <cuda_runtime.h>

// x <- gelu(x + depthwise_conv3d_3x3x3(x)) x8.  [4,32,64,64,64] fp32.
// Fused 8-step cluster kernel; 128 threads; 2 output H-rows per thread;
// cp.async DEPTH-2 pipeline (wait_group 1); centers carried in registers.

#define CC    32
#define VOL   (64*64*64)
#define RS    72                 // words per slab row
#define RSB   (RS*4)             // 288 bytes per row
#define BUFB  (18*RSB)           // 5184 bytes per plane buffer

typedef unsigned long long u64;
typedef unsigned int u32;

__device__ float  g_sA[4 * CC * VOL];
__device__ float  g_sB[4 * CC * VOL];
__device__ __align__(16) float4 g_zero4 = {0.f, 0.f, 0.f, 0.f};

// ---------- packed f32x2 helpers ----------
__device__ __forceinline__ u64 pack2(float lo, float hi) {
    u64 r; asm("mov.b64 %0, {%1, %2};" : "=l"(r) : "f"(lo), "f"(hi)); return r;
}
__device__ __forceinline__ void unpack2(u64 v, float& lo, float& hi) {
    asm("mov.b64 {%0, %1}, %2;" : "=f"(lo), "=f"(hi) : "l"(v));
}
__device__ __forceinline__ void fma2(u64& acc, u64 a, u64 b) {
    asm("fma.rn.f32x2 %0, %1, %2, %0;" : "+l"(acc) : "l"(a), "l"(b));
}
__device__ __forceinline__ void mul2(u64& d, u64 a, u64 b) {
    asm("mul.rn.f32x2 %0, %1, %2;" : "=l"(d) : "l"(a), "l"(b));
}
__device__ __forceinline__ u64 add2(u64 a, u64 b) {
    u64 r; asm("add.rn.f32x2 %0, %1, %2;" : "=l"(r) : "l"(a), "l"(b)); return r;
}

// ---------- volatile SMEM loads (no CSE across planes / no hoist over bars) ----------
#define LDSP(x, y, base, IMM)                                            \
    asm volatile("ld.shared.v2.u64 {%0, %1}, [%2+%3];"                   \
                 : "=l"(x), "=l"(y) : "r"(base), "n"(IMM))
#define LDS1(x, base, IMM)                                               \
    asm volatile("ld.shared.u64 %0, [%1+%2];"                            \
                 : "=l"(x) : "r"(base), "n"(IMM))

// ---------- cp.async ----------
#define CPA16(dst, src)                                                  \
    asm volatile("cp.async.cg.shared.global [%0], [%1], 16;"             \
                 :: "r"(dst), "l"(src))
#define CPA16P(pred, dst, src)                                           \
    asm volatile("{ .reg .pred p; setp.ne.s32 p, %0, 0;"                 \
                 "  @p cp.async.cg.shared.global [%1], [%2], 16; }"      \
                 :: "r"(pred), "r"(dst), "l"(src))
#define CPCOMMIT() asm volatile("cp.async.commit_group;")
#define CPWAIT0()  asm volatile("cp.async.wait_group 0;")
#define CPWAIT1()  asm volatile("cp.async.wait_group 1;")

// Exact-erf GELU via A&S 7.1.27 (abs err ~3e-7; tol 1e-3). One MUFU.
__device__ __forceinline__ float gelu16(float x) {
    float a = fabsf(x) * 0.70710678118654752440f;
    float p = fmaf(0.0000430638f, a, 0.0002765672f);
    p = fmaf(p, a, 0.0001520143f);
    p = fmaf(p, a, 0.0092705272f);
    p = fmaf(p, a, 0.0422820123f);
    p = fmaf(p, a, 0.0705230784f);
    p = fmaf(p, a, 1.0f);
    float r; asm("rcp.approx.f32 %0, %1;" : "=f"(r) : "f"(p));
    r = r * r; r = r * r; r = r * r; r = r * r;      // p^-16
    float er = 1.0f - r;
    er = copysignf(er, x);
    return 0.5f * fmaf(x, er, x);
}

// One input row's 5 stencil windows: 2x LDS.64 edges + 1x LDS.128 center.
#define LOADQ(OFF)                                                       \
    u64 E1, Q1, Q3, F0;                                                  \
    LDS1(E1, rB, (OFF) + 8);                                             \
    LDSP(Q1, Q3, rB, (OFF) + 16);                                        \
    LDS1(F0, rB, (OFF) + 32);                                            \
    float fm, fp, f0, f1, f2, f3, dm0, dm1;                              \
    unpack2(E1, dm0, fm);                                                \
    unpack2(F0, fp, dm1);                                                \
    unpack2(Q1, f0, f1);                                                 \
    unpack2(Q3, f2, f3);                                                 \
    u64 Q0 = pack2(fm, f0), Q2 = pack2(f1, f2), Q4 = pack2(f3, fp);      \
    (void)dm0; (void)dm1;

#define FMA6(S0, S1, WB)                                                 \
    fma2(S0, W2[(WB)+0], Q0); fma2(S1, W2[(WB)+0], Q2);                  \
    fma2(S0, W2[(WB)+1], Q1); fma2(S1, W2[(WB)+1], Q3);                  \
    fma2(S0, W2[(WB)+2], Q2); fma2(S1, W2[(WB)+2], Q4);
#define MUL6(S0, S1, WB)                                                 \
    mul2(S0, W2[(WB)+0], Q0); mul2(S1, W2[(WB)+0], Q2);                  \
    fma2(S0, W2[(WB)+1], Q1); fma2(S1, W2[(WB)+1], Q3);                  \
    fma2(S0, W2[(WB)+2], Q2); fma2(S1, W2[(WB)+2], Q4);

// Locals use reserved _names (macro-capture bug class, round 12).
#define STORE4(A0, A1, C0, C1, PTR)                                      \
    {                                                                    \
        u64 _t0 = add2(A0, C0), _t1 = add2(A1, C1);                      \
        float _o0, _o1, _o2, _o3;                                        \
        unpack2(_t0, _o0, _o1); unpack2(_t1, _o2, _o3);                  \
        float4 _ov = make_float4(gelu16(_o0), gelu16(_o1),               \
                                 gelu16(_o2), gelu16(_o3));              \
        *(float4*)(PTR) = _ov;                                           \
    }

// One plane at buffer byte offset SB: 4 LOADQ rows -> 2 output rows.
// X completes (kz2), Y mid (kz1), Z fresh (kz0, MUL at first touch).
// Captures this plane's residual centers (Q1,Q3 at rows 1,2) into CV quad.
#define PLANE(SB, X0,X1,X2,X3, Y0,Y1,Y2,Y3, Z0,Z1,Z2,Z3, CV0,CV1,CV2,CV3) \
    { LOADQ((SB))           MUL6(Z0,Z1,0)  FMA6(Y0,Y1,9)   FMA6(X0,X1,18) } \
    { LOADQ((SB) + RSB)     CV0 = Q1; CV1 = Q3;                           \
                            FMA6(X0,X1,21) FMA6(Y0,Y1,12)  FMA6(Z0,Z1,3)  \
                            MUL6(Z2,Z3,0)  FMA6(Y2,Y3,9)   FMA6(X2,X3,18) } \
    { LOADQ((SB) + 2*RSB)   CV2 = Q1; CV3 = Q3;                           \
                            FMA6(X0,X1,24) FMA6(Y0,Y1,15)  FMA6(Z0,Z1,6)  \
                            FMA6(X2,X3,21) FMA6(Y2,Y3,12)  FMA6(Z2,Z3,3) } \
    { LOADQ((SB) + 3*RSB)   FMA6(X2,X3,24) FMA6(Y2,Y3,15)  FMA6(Z2,Z3,6) }

// Window p: wait_group (1 keeps plane p+1 in flight; plane p resident),
// barrier, prefetch plane p+2 into buffer SBN2=((p+2)%3) (reader-free:
// its last reader finished before this barrier), compute plane p from
// SB=(p%3), store out(p-1) with carried centers, carry plane-p centers.
#define WINDOW(SB, SBN2, X0,X1,X2,X3, Y0,Y1,Y2,Y3, Z0,Z1,Z2,Z3, DOST, DOPF, WAITN) \
    do {                                                                 \
        if ((WAITN) == 0) CPWAIT0(); else CPWAIT1();                     \
        __syncthreads();                                                 \
        if (DOPF) {                                                      \
            CPA16(d0 + (SBN2), p0); CPA16(d1 + (SBN2), p1);              \
            CPA16P(isB, d2 + (SBN2), p2);                                \
            CPCOMMIT();                                                  \
            p0 += st0; p1 += st1; p2 += st2;                             \
        }                                                                \
        u64 cv0, cv1, cv2, cv3;                                          \
        PLANE((SB), X0,X1,X2,X3, Y0,Y1,Y2,Y3, Z0,Z1,Z2,Z3,               \
              cv0,cv1,cv2,cv3)                                           \
        if (DOST) {                                                      \
            STORE4(X0, X1, cen0, cen1, optr);                            \
            STORE4(X2, X3, cen2, cen3, optr + 64);                       \
            optr += 4096;                                                \
        }                                                                \
        cen0 = cv0; cen1 = cv1; cen2 = cv2; cen3 = cv3;                  \
    } while (0)

// Cluster of 4 = the 4 H-chunks of one (b,c); halos only cross H-chunks.
__global__ void __launch_bounds__(128, 4) __cluster_dims__(4, 1, 1)
fused_kernel(const float* __restrict__ x, float* __restrict__ outF,
             const float* __restrict__ wts,
             float* __restrict__ sA, float* __restrict__ sB)
{
    const int tid = threadIdx.x;             // 0..127
    const int tx  = tid & 15;                // w quad
    const int ty  = tid >> 4;                // 0..7: output rows 2ty, 2ty+1
    const int h0  = blockIdx.x * 16;
    const int c   = blockIdx.y;
    const int b   = blockIdx.z;
    const size_t volOff = (size_t)(b * CC + c) * VOL;

    u64 W2[27];
#pragma unroll
    for (int i = 0; i < 27; ++i) {
        float w = __ldg(&wts[c * 27 + i]);
        W2[i] = pack2(w, w);
    }

    // 3 rotating plane buffers; row: words 0..2 pad, 3 = left halo(0),
    // 4..67 data, 68 = right halo(0), 69..71 pad.
    __shared__ __align__(16) float sl[3 * 18 * RS];

    if (tid < 108) {                         // zero halo words once
        int buf = tid / 36, k = tid % 36;
        sl[buf * (18 * RS) + (k % 18) * RS + (k < 18 ? 3 : 68)] = 0.f;
    }

    const u32 sbase = (u32)__cvta_generic_to_shared(sl);
    const u32 rB    = sbase + ty * 2 * RSB + 16 * tx;   // word 4tx of row 2ty

    // Loader: thread covers 16B chunks of rows lr, lr+8, (tid<32: lr+16).
    const int lr = tid >> 4, lq = tid & 15;
    const int gh0 = h0 - 1 + lr;
    const int gh1 = gh0 + 8;
    const int gh2 = gh0 + 16;
    const bool v0 = (gh0 >= 0) && (gh0 < 64);
    const bool v1 = (gh1 < 64);                         // gh1 >= 7 always
    const bool v2 = (tid < 32) && (gh2 < 64);
    const int isB = (tid < 32) ? 1 : 0;
    const int of0 = gh0 * 16 + lq, of1 = gh1 * 16 + lq, of2 = gh2 * 16 + lq;
    const int st0 = v0 ? 1024 : 0, st1 = v1 ? 1024 : 0, st2 = v2 ? 1024 : 0;

    const u32 d0 = sbase + (lr * RS + 4 + 4 * lq) * 4;
    const u32 d1 = d0 + 8 * RSB;
    const u32 d2 = d0 + 16 * RSB;

    const int outOfs = (h0 + 2 * ty) * 64 + 4 * tx;

    const float* sin = x;

#pragma unroll 1
    for (int s = 0; s < 8; ++s) {
        float* sout = (s == 7) ? outF : ((s & 1) ? sB : sA);
        const float* vin = sin + volOff;

        const float4* p0 = v0 ? (const float4*)vin + of0 : &g_zero4;
        const float4* p1 = v1 ? (const float4*)vin + of1 : &g_zero4;
        const float4* p2 = v2 ? (const float4*)vin + of2 : &g_zero4;
        float* optr = (sout + volOff) + outOfs;

        // Prologue: plane 0 -> buf0, plane 1 -> buf1 (two groups in flight).
        CPA16(d0, p0); CPA16(d1, p1); CPA16P(isB, d2, p2);
        CPCOMMIT();
        CPA16(d0 + BUFB, p0 + st0); CPA16(d1 + BUFB, p1 + st1);
        CPA16P(isB, d2 + BUFB, p2 + st2);
        CPCOMMIT();
        p0 += 2 * st0; p1 += 2 * st1; p2 += 2 * st2;

        // s0..s2 role quads + carried center quad.
        u64 s00=0,s01=0,s02=0,s03=0, s10=0,s11=0,s12=0,s13=0,
            s20=0,s21=0,s22=0,s23=0;
        u64 cen0=0, cen1=0, cen2=0, cen3=0;

        // Window p: X=s[(p+2)%3], Y=s[p%3], Z=s[(p+1)%3];
        // SB=(p%3)*BUFB, prefetch dst SBN2=((p+2)%3)*BUFB.
        WINDOW(0, 2*BUFB, s20,s21,s22,s23, s00,s01,s02,s03,
               s10,s11,s12,s13, false, true, 1);                     // p=0
#pragma unroll 1
        for (int i = 0; i < 20; ++i) {                               // p=1..60
            WINDOW(BUFB, 0, s00,s01,s02,s03, s10,s11,s12,s13,
                   s20,s21,s22,s23, true, true, 1);                  // p%3==1
            WINDOW(2*BUFB, BUFB, s10,s11,s12,s13, s20,s21,s22,s23,
                   s00,s01,s02,s03, true, true, 1);                  // p%3==2
            WINDOW(0, 2*BUFB, s20,s21,s22,s23, s00,s01,s02,s03,
                   s10,s11,s12,s13, true, true, 1);                  // p%3==0
        }
        WINDOW(BUFB, 0, s00,s01,s02,s03, s10,s11,s12,s13,
               s20,s21,s22,s23, true, true, 1);                      // p=61 (issues 63)
        WINDOW(2*BUFB, BUFB, s10,s11,s12,s13, s20,s21,s22,s23,
               s00,s01,s02,s03, true, false, 1);                     // p=62
        WINDOW(0, 2*BUFB, s20,s21,s22,s23, s00,s01,s02,s03,
               s10,s11,s12,s13, true, false, 0);                     // p=63

        // out(63): kz2 (plane 64) = 0; partial = Y of w63 = s0 quad;
        // centers = plane 63's, carried in cen after w63.
        STORE4(s00, s01, cen0, cen1, optr);
        STORE4(s02, s03, cen2, cen3, optr + 64);

        if (s < 7) {
            __threadfence();
            asm volatile("barrier.cluster.arrive.aligned;" ::: "memory");
            asm volatile("barrier.cluster.wait.aligned;"   ::: "memory");
        }
        sin = sout;
    }
}

extern "C" void kernel_launch(void* const* d_in, const int* in_sizes, int n_in,
                              void* d_out, int out_size)
{
    const float* x = (const float*)d_in[0];
    const float* w = (const float*)d_in[1];
    float* out = (float*)d_out;

    float *sA = nullptr, *sB = nullptr;
    cudaGetSymbolAddress((void**)&sA, g_sA);
    cudaGetSymbolAddress((void**)&sB, g_sB);

    dim3 grid(4, CC, 4);    // x-dim (H-chunks) grouped into clusters of 4
    dim3 blk(128);
    fused_kernel<<<grid, blk>>>(x, out, w, sA, sB);
}

// round 17
// speedup vs baseline: 1.0624x; 1.0457x over previous
#include <cuda_runtime.h>

// x <- gelu(x + depthwise_conv3d_3x3x3(x)) x8.  [4,32,64,64,64] fp32.
// Fused 8-step cluster kernel; 128 threads; 2 output H-rows per thread;
// cp.async loader (depth-1); single-copy slabs; 3 rotating plane buffers.
// (Champion r14 config: best measured kernel time 705.3us.)

#define CC    32
#define VOL   (64*64*64)
#define RS    72                 // words per slab row
#define RSB   (RS*4)             // 288 bytes per row
#define BUFB  (18*RSB)           // 5184 bytes per plane buffer

typedef unsigned long long u64;
typedef unsigned int u32;

__device__ float  g_sA[4 * CC * VOL];
__device__ float  g_sB[4 * CC * VOL];
__device__ __align__(16) float4 g_zero4 = {0.f, 0.f, 0.f, 0.f};

// ---------- packed f32x2 helpers ----------
__device__ __forceinline__ u64 pack2(float lo, float hi) {
    u64 r; asm("mov.b64 %0, {%1, %2};" : "=l"(r) : "f"(lo), "f"(hi)); return r;
}
__device__ __forceinline__ void unpack2(u64 v, float& lo, float& hi) {
    asm("mov.b64 {%0, %1}, %2;" : "=f"(lo), "=f"(hi) : "l"(v));
}
__device__ __forceinline__ void fma2(u64& acc, u64 a, u64 b) {
    asm("fma.rn.f32x2 %0, %1, %2, %0;" : "+l"(acc) : "l"(a), "l"(b));
}
__device__ __forceinline__ void mul2(u64& d, u64 a, u64 b) {
    asm("mul.rn.f32x2 %0, %1, %2;" : "=l"(d) : "l"(a), "l"(b));
}
__device__ __forceinline__ u64 add2(u64 a, u64 b) {
    u64 r; asm("add.rn.f32x2 %0, %1, %2;" : "=l"(r) : "l"(a), "l"(b)); return r;
}

// ---------- volatile SMEM loads (no CSE across planes / no hoist over bars) ----------
#define LDSP(x, y, base, IMM)                                            \
    asm volatile("ld.shared.v2.u64 {%0, %1}, [%2+%3];"                   \
                 : "=l"(x), "=l"(y) : "r"(base), "n"(IMM))
#define LDS1(x, base, IMM)                                               \
    asm volatile("ld.shared.u64 %0, [%1+%2];"                            \
                 : "=l"(x) : "r"(base), "n"(IMM))

// ---------- cp.async ----------
#define CPA16(dst, src)                                                  \
    asm volatile("cp.async.cg.shared.global [%0], [%1], 16;"             \
                 :: "r"(dst), "l"(src))
#define CPA16P(pred, dst, src)                                           \
    asm volatile("{ .reg .pred p; setp.ne.s32 p, %0, 0;"                 \
                 "  @p cp.async.cg.shared.global [%1], [%2], 16; }"      \
                 :: "r"(pred), "r"(dst), "l"(src))
#define CPCOMMIT() asm volatile("cp.async.commit_group;")
#define CPWAIT0()  asm volatile("cp.async.wait_group 0;")

// Exact-erf GELU via A&S 7.1.27: erf(a) = 1 - (1 + a1 a + ... + a6 a^6)^-16,
// max abs err ~3e-7 (tol 1e-3). One MUFU (rcp); Horner chain is FFMA-imm.
__device__ __forceinline__ float gelu16(float x) {
    float a = fabsf(x) * 0.70710678118654752440f;
    float p = fmaf(0.0000430638f, a, 0.0002765672f);
    p = fmaf(p, a, 0.0001520143f);
    p = fmaf(p, a, 0.0092705272f);
    p = fmaf(p, a, 0.0422820123f);
    p = fmaf(p, a, 0.0705230784f);
    p = fmaf(p, a, 1.0f);
    float r; asm("rcp.approx.f32 %0, %1;" : "=f"(r) : "f"(p));
    r = r * r; r = r * r; r = r * r; r = r * r;      // p^-16
    float er = 1.0f - r;
    er = copysignf(er, x);
    return 0.5f * fmaf(x, er, x);
}

// One input row's 5 stencil windows: 2x LDS.64 edges + 1x LDS.128 center.
#define LOADQ(OFF)                                                       \
    u64 E1, Q1, Q3, F0;                                                  \
    LDS1(E1, rB, (OFF) + 8);                                             \
    LDSP(Q1, Q3, rB, (OFF) + 16);                                        \
    LDS1(F0, rB, (OFF) + 32);                                            \
    float fm, fp, f0, f1, f2, f3, dm0, dm1;                              \
    unpack2(E1, dm0, fm);                                                \
    unpack2(F0, fp, dm1);                                                \
    unpack2(Q1, f0, f1);                                                 \
    unpack2(Q3, f2, f3);                                                 \
    u64 Q0 = pack2(fm, f0), Q2 = pack2(f1, f2), Q4 = pack2(f3, fp);      \
    (void)dm0; (void)dm1;

#define FMA6(S0, S1, WB)                                                 \
    fma2(S0, W2[(WB)+0], Q0); fma2(S1, W2[(WB)+0], Q2);                  \
    fma2(S0, W2[(WB)+1], Q1); fma2(S1, W2[(WB)+1], Q3);                  \
    fma2(S0, W2[(WB)+2], Q2); fma2(S1, W2[(WB)+2], Q4);
#define MUL6(S0, S1, WB)                                                 \
    mul2(S0, W2[(WB)+0], Q0); mul2(S1, W2[(WB)+0], Q2);                  \
    fma2(S0, W2[(WB)+1], Q1); fma2(S1, W2[(WB)+1], Q3);                  \
    fma2(S0, W2[(WB)+2], Q2); fma2(S1, W2[(WB)+2], Q4);

// Locals use reserved _names (macro-capture bug class, round 12).
#define STORE4(A0, A1, C0, C1, PTR)                                      \
    {                                                                    \
        u64 _t0 = add2(A0, C0), _t1 = add2(A1, C1);                      \
        float _o0, _o1, _o2, _o3;                                        \
        unpack2(_t0, _o0, _o1); unpack2(_t1, _o2, _o3);                  \
        float4 _ov = make_float4(gelu16(_o0), gelu16(_o1),               \
                                 gelu16(_o2), gelu16(_o3));              \
        *(float4*)(PTR) = _ov;                                           \
    }

// Window p: wait plane p's cp.async, barrier, issue cp.async p+1 (disjoint buf),
// compute 4 input rows (2 output rows x 3 pipeline stages), store out(p-1).
// X completes out(p-1) [kz2], Y = out(p) [kz1], Z = out(p+1) fresh [kz0].
#define WINDOW(SB, SBN, SBC, X0,X1,X2,X3, Y0,Y1,Y2,Y3, Z0,Z1,Z2,Z3, DOST, DOPF) \
    do {                                                                 \
        CPWAIT0();                                                       \
        __syncthreads();                                                 \
        if (DOPF) {                                                      \
            CPA16(d0 + (SBN), p0); CPA16(d1 + (SBN), p1);                \
            CPA16P(isB, d2 + (SBN), p2);                                 \
            CPCOMMIT();                                                  \
            p0 += st0; p1 += st1; p2 += st2;                             \
        }                                                                \
        u64 c0, c1, c2, c3;                                              \
        if (DOST) {                                                      \
            LDSP(c0, c1, rB, (SBC) + RSB + 16);                          \
            LDSP(c2, c3, rB, (SBC) + 2 * RSB + 16);                      \
        }                                                                \
        { LOADQ((SB))           MUL6(Z0,Z1,0)  FMA6(Y0,Y1,9)   FMA6(X0,X1,18) }  \
        { LOADQ((SB) + RSB)     FMA6(Z0,Z1,3)  FMA6(Y0,Y1,12)  FMA6(X0,X1,21)    \
                                MUL6(Z2,Z3,0)  FMA6(Y2,Y3,9)   FMA6(X2,X3,18) }  \
        { LOADQ((SB) + 2*RSB)   FMA6(Z0,Z1,6)  FMA6(Y0,Y1,15)  FMA6(X0,X1,24)    \
                                FMA6(Z2,Z3,3)  FMA6(Y2,Y3,12)  FMA6(X2,X3,21) }  \
        { LOADQ((SB) + 3*RSB)   FMA6(Z2,Z3,6)  FMA6(Y2,Y3,15)  FMA6(X2,X3,24) }  \
        if (DOST) {                                                      \
            STORE4(X0, X1, c0, c1, optr);                                \
            STORE4(X2, X3, c2, c3, optr + 64);                           \
            optr += 4096;                                                \
        }                                                                \
    } while (0)

// Cluster of 4 = the 4 H-chunks of one (b,c); halos only cross H-chunks.
__global__ void __launch_bounds__(128, 4) __cluster_dims__(4, 1, 1)
fused_kernel(const float* __restrict__ x, float* __restrict__ outF,
             const float* __restrict__ wts,
             float* __restrict__ sA, float* __restrict__ sB)
{
    const int tid = threadIdx.x;             // 0..127
    const int tx  = tid & 15;                // w quad
    const int ty  = tid >> 4;                // 0..7: output rows 2ty, 2ty+1
    const int h0  = blockIdx.x * 16;
    const int c   = blockIdx.y;
    const int b   = blockIdx.z;
    const size_t volOff = (size_t)(b * CC + c) * VOL;

    u64 W2[27];
#pragma unroll
    for (int i = 0; i < 27; ++i) {
        float w = __ldg(&wts[c * 27 + i]);
        W2[i] = pack2(w, w);
    }

    // 3 rotating plane buffers; row: words 0..2 pad, 3 = left halo(0),
    // 4..67 data, 68 = right halo(0), 69..71 pad.
    __shared__ __align__(16) float sl[3 * 18 * RS];

    if (tid < 108) {                         // zero halo words once
        int buf = tid / 36, k = tid % 36;
        sl[buf * (18 * RS) + (k % 18) * RS + (k < 18 ? 3 : 68)] = 0.f;
    }

    const u32 sbase = (u32)__cvta_generic_to_shared(sl);
    const u32 rB    = sbase + ty * 2 * RSB + 16 * tx;   // word 4tx of row 2ty

    // Loader: thread covers 16B chunks of rows lr, lr+8, (tid<32: lr+16).
    const int lr = tid >> 4, lq = tid & 15;
    const int gh0 = h0 - 1 + lr;
    const int gh1 = gh0 + 8;
    const int gh2 = gh0 + 16;
    const bool v0 = (gh0 >= 0) && (gh0 < 64);
    const bool v1 = (gh1 < 64);                         // gh1 >= 7 always
    const bool v2 = (tid < 32) && (gh2 < 64);
    const int isB = (tid < 32) ? 1 : 0;
    const int of0 = gh0 * 16 + lq, of1 = gh1 * 16 + lq, of2 = gh2 * 16 + lq;
    const int st0 = v0 ? 1024 : 0, st1 = v1 ? 1024 : 0, st2 = v2 ? 1024 : 0;

    const u32 d0 = sbase + (lr * RS + 4 + 4 * lq) * 4;
    const u32 d1 = d0 + 8 * RSB;
    const u32 d2 = d0 + 16 * RSB;

    const int outOfs = (h0 + 2 * ty) * 64 + 4 * tx;

    const float* sin = x;

#pragma unroll 1
    for (int s = 0; s < 8; ++s) {
        float* sout = (s == 7) ? outF : ((s & 1) ? sB : sA);
        const float* vin = sin + volOff;

        const float4* p0 = v0 ? (const float4*)vin + of0 : &g_zero4;
        const float4* p1 = v1 ? (const float4*)vin + of1 : &g_zero4;
        const float4* p2 = v2 ? (const float4*)vin + of2 : &g_zero4;
        float* optr = (sout + volOff) + outOfs;

        // Prologue: plane 0 -> buf0.
        CPA16(d0, p0); CPA16(d1, p1); CPA16P(isB, d2, p2);
        CPCOMMIT();
        p0 += st0; p1 += st1; p2 += st2;

        // s0..s2 role quads (out-row0 h0,h1, out-row1 h0,h1).
        u64 s00=0,s01=0,s02=0,s03=0, s10=0,s11=0,s12=0,s13=0,
            s20=0,s21=0,s22=0,s23=0;

        // Window p: X=s[(p+2)%3], Y=s[p%3], Z=s[(p+1)%3]; bufs SB=p%3 etc.
        WINDOW(0, BUFB, 2*BUFB, s20,s21,s22,s23, s00,s01,s02,s03,
               s10,s11,s12,s13, false, true);                        // p=0
#pragma unroll 1
        for (int i = 0; i < 20; ++i) {                               // p=1..60
            WINDOW(BUFB, 2*BUFB, 0, s00,s01,s02,s03, s10,s11,s12,s13,
                   s20,s21,s22,s23, true, true);                     // p%3==1
            WINDOW(2*BUFB, 0, BUFB, s10,s11,s12,s13, s20,s21,s22,s23,
                   s00,s01,s02,s03, true, true);                     // p%3==2
            WINDOW(0, BUFB, 2*BUFB, s20,s21,s22,s23, s00,s01,s02,s03,
                   s10,s11,s12,s13, true, true);                     // p%3==0
        }
        WINDOW(BUFB, 2*BUFB, 0, s00,s01,s02,s03, s10,s11,s12,s13,
               s20,s21,s22,s23, true, true);                         // p=61
        WINDOW(2*BUFB, 0, BUFB, s10,s11,s12,s13, s20,s21,s22,s23,
               s00,s01,s02,s03, true, true);                         // p=62
        WINDOW(0, BUFB, 2*BUFB, s20,s21,s22,s23, s00,s01,s02,s03,
               s10,s11,s12,s13, true, false);                        // p=63

        // out(63): kz2 (plane 64) = 0; partial = Y of window 63 = s0;
        // centers = plane 63 (buf0) rows 2ty+1, 2ty+2.
        {
            u64 c0, c1, c2, c3;
            LDSP(c0, c1, rB, RSB + 16);
            LDSP(c2, c3, rB, 2 * RSB + 16);
            STORE4(s00, s01, c0, c1, optr);
            STORE4(s02, s03, c2, c3, optr + 64);
        }

        if (s < 7) {
            __threadfence();
            asm volatile("barrier.cluster.arrive.aligned;" ::: "memory");
            asm volatile("barrier.cluster.wait.aligned;"   ::: "memory");
        }
        sin = sout;
    }
}

extern "C" void kernel_launch(void* const* d_in, const int* in_sizes, int n_in,
                              void* d_out, int out_size)
{
    const float* x = (const float*)d_in[0];
    const float* w = (const float*)d_in[1];
    float* out = (float*)d_out;

    float *sA = nullptr, *sB = nullptr;
    cudaGetSymbolAddress((void**)&sA, g_sA);
    cudaGetSymbolAddress((void**)&sB, g_sB);

    dim3 grid(4, CC, 4);    // x-dim (H-chunks) grouped into clusters of 4
    dim3 blk(128);
    fused_kernel<<<grid, blk>>>(x, out, w, sA, sB);
}